// round 4
// baseline (speedup 1.0000x reference)
#include <cuda_runtime.h>
#include <cuda_bf16.h>
#include <cstdint>

// ---------------------------------------------------------------------------
// BitLinear forward on base sm_100 (tcgen05 unavailable at this PTX target):
//   1) ternary weight quant  -> int8 {-1,0,1} + per-row scale
//   2) int8 activation quant -> int8 [-128,127] + per-row scale
//   3) int8 GEMM via mma.sync.m16n8k32.s8 (exact integer accumulation)
//   4) fused float rescale epilogue
// M = 8192, N = 4096, K = 4096.
// R4: software-pipeline ldmatrix fragment loads across ks (double-buffered
//     register fragments) to hide LDS latency under the MMA stream.
// ---------------------------------------------------------------------------

#define K_DIM 4096
#define N_DIM 4096
#define M_ROWS_MAX 8192

#define BM 128
#define BN 256
#define BK 128              // int8 elements == bytes
#define STAGES 3
#define KT (K_DIM / BK)     // 32

#define A_BYTES (BM * BK)               // 16384
#define B_BYTES (BN * BK)               // 32768
#define STAGE_BYTES (A_BYTES + B_BYTES) // 49152
#define GEMM_SMEM (STAGES * STAGE_BYTES) // 147456

// Scratch (device globals; runtime allocation is forbidden)
__device__ int8_t g_aq8[(size_t)M_ROWS_MAX * K_DIM];   // 32 MB
__device__ int8_t g_wq8[(size_t)N_DIM * K_DIM];        // 16 MB
__device__ float  g_ascale[M_ROWS_MAX];                // max|x| + eps
__device__ float  g_wsa[N_DIM];                        // w_scale * alpha / 127

// ---------------------------------------------------------------------------
// PTX helpers (base-sm_100 legal: cp.async, ldmatrix, mma.sync)
// ---------------------------------------------------------------------------
__device__ __forceinline__ uint32_t smem_u32(const void* p) {
    uint32_t a;
    asm("{ .reg .u64 t; cvta.to.shared.u64 t, %1; cvt.u32.u64 %0, t; }"
        : "=r"(a) : "l"(p));
    return a;
}

__device__ __forceinline__ void cp_async16(uint32_t dst, const void* src) {
    asm volatile("cp.async.cg.shared.global [%0], [%1], 16;"
                 :: "r"(dst), "l"(src) : "memory");
}
__device__ __forceinline__ void cp_commit() {
    asm volatile("cp.async.commit_group;" ::: "memory");
}
template <int N>
__device__ __forceinline__ void cp_wait() {
    asm volatile("cp.async.wait_group %0;" :: "n"(N) : "memory");
}

__device__ __forceinline__ void ldsm_x4(uint32_t* r, uint32_t addr) {
    asm volatile("ldmatrix.sync.aligned.m8n8.x4.shared.b16 {%0,%1,%2,%3}, [%4];"
                 : "=r"(r[0]), "=r"(r[1]), "=r"(r[2]), "=r"(r[3]) : "r"(addr));
}

__device__ __forceinline__ void mma_s8(int* d, const uint32_t* a, const uint32_t* b) {
    asm volatile(
        "mma.sync.aligned.m16n8k32.row.col.s32.s8.s8.s32 "
        "{%0,%1,%2,%3}, {%4,%5,%6,%7}, {%8,%9}, {%0,%1,%2,%3};"
        : "+r"(d[0]), "+r"(d[1]), "+r"(d[2]), "+r"(d[3])
        : "r"(a[0]), "r"(a[1]), "r"(a[2]), "r"(a[3]), "r"(b[0]), "r"(b[1]));
}

// swizzle: 16B chunk within a 128B row XOR'ed by (row & 7)
#define SWZ128(x) ((x) ^ (((x) >> 3) & 0x70))

// ---------------------------------------------------------------------------
// Block reductions
// ---------------------------------------------------------------------------
__device__ __forceinline__ float block_max(float v) {
    __shared__ float sh[8];
    #pragma unroll
    for (int o = 16; o; o >>= 1) v = fmaxf(v, __shfl_xor_sync(0xffffffffu, v, o));
    if ((threadIdx.x & 31) == 0) sh[threadIdx.x >> 5] = v;
    __syncthreads();
    if (threadIdx.x < 32) {
        float t = (threadIdx.x < 8) ? sh[threadIdx.x] : 0.0f;
        #pragma unroll
        for (int o = 4; o; o >>= 1) t = fmaxf(t, __shfl_xor_sync(0xffffffffu, t, o));
        if (threadIdx.x == 0) sh[0] = t;
    }
    __syncthreads();
    return sh[0];
}

__device__ __forceinline__ double block_sum_d(double v) {
    __shared__ double sh[8];
    #pragma unroll
    for (int o = 16; o; o >>= 1) v += __shfl_xor_sync(0xffffffffu, v, o);
    if ((threadIdx.x & 31) == 0) sh[threadIdx.x >> 5] = v;
    __syncthreads();
    if (threadIdx.x < 32) {
        double t = (threadIdx.x < 8) ? sh[threadIdx.x] : 0.0;
        #pragma unroll
        for (int o = 4; o; o >>= 1) t += __shfl_xor_sync(0xffffffffu, t, o);
        if (threadIdx.x == 0) sh[0] = t;
    }
    __syncthreads();
    return sh[0];
}

// ---------------------------------------------------------------------------
// Weight quantization: one block per output channel (4096 elems)
// ---------------------------------------------------------------------------
__global__ void __launch_bounds__(256) wquant_kernel(const float* __restrict__ w,
                                                     const float* __restrict__ alpha) {
    const int row = blockIdx.x;
    const float4* wr = (const float4*)(w + (size_t)row * K_DIM);
    float4 v[4];
    double acc = 0.0;
    #pragma unroll
    for (int i = 0; i < 4; ++i) {
        v[i] = wr[threadIdx.x + 256 * i];
        acc += (double)fabsf(v[i].x) + (double)fabsf(v[i].y) +
               (double)fabsf(v[i].z) + (double)fabsf(v[i].w);
    }
    double total = block_sum_d(acc);
    float scale = (float)(total / 4096.0) + 1e-8f;   // mean(|w|) + EPS
    if (threadIdx.x == 0)
        g_wsa[row] = scale * (alpha[row] * (1.0f / 127.0f));

    uint32_t* dst = (uint32_t*)(g_wq8 + (size_t)row * K_DIM);
    #pragma unroll
    for (int i = 0; i < 4; ++i) {
        float q[4] = {v[i].x, v[i].y, v[i].z, v[i].w};
        uint32_t p = 0;
        #pragma unroll
        for (int j = 0; j < 4; ++j) {
            float wn = __fdiv_rn(q[j], scale);
            float r = rintf(wn);                      // round-half-even like jnp
            r = fminf(fmaxf(r, -1.0f), 1.0f);         // clip AFTER round
            p |= ((uint32_t)((int)r & 0xff)) << (8 * j);
        }
        dst[threadIdx.x + 256 * i] = p;
    }
}

// ---------------------------------------------------------------------------
// Activation quantization: one block per token row (4096 elems)
// ---------------------------------------------------------------------------
__global__ void __launch_bounds__(256) aquant_kernel(const float* __restrict__ x) {
    const int row = blockIdx.x;
    const float4* xr = (const float4*)(x + (size_t)row * K_DIM);
    float4 v[4];
    float mx = 0.0f;
    #pragma unroll
    for (int i = 0; i < 4; ++i) {
        v[i] = xr[threadIdx.x + 256 * i];
        mx = fmaxf(mx, fmaxf(fmaxf(fabsf(v[i].x), fabsf(v[i].y)),
                             fmaxf(fabsf(v[i].z), fabsf(v[i].w))));
    }
    mx = block_max(mx);
    float s = mx + 1e-8f;                              // a_scale (max is exact)
    if (threadIdx.x == 0) g_ascale[row] = s;

    uint32_t* dst = (uint32_t*)(g_aq8 + (size_t)row * K_DIM);
    #pragma unroll
    for (int i = 0; i < 4; ++i) {
        float q[4] = {v[i].x, v[i].y, v[i].z, v[i].w};
        uint32_t p = 0;
        #pragma unroll
        for (int j = 0; j < 4; ++j) {
            // EXACT op order of reference: (x / a_scale) * 127 ; clip ; round
            float t = __fdiv_rn(q[j], s) * 127.0f;
            t = fminf(fmaxf(t, -128.0f), 127.0f);
            t = rintf(t);
            p |= ((uint32_t)((int)t & 0xff)) << (8 * j);
        }
        dst[threadIdx.x + 256 * i] = p;
    }
}

// ---------------------------------------------------------------------------
// int8 GEMM: out[m][n] = (sum_k aq[m][k]*wq[n][k]) * ascale[m] * wsa[n]
// CTA 128x256, warp 64x64, 3-stage cp.async pipeline,
// register-double-buffered ldmatrix fragments, mma.sync.m16n8k32.s8.
// ---------------------------------------------------------------------------
__device__ __forceinline__ void load_stage(uint32_t sBase, int kt,
                                           int mBase, int nBase, int tid) {
    const uint32_t sA = sBase;
    const uint32_t sB = sBase + A_BYTES;
    const int8_t* gA = g_aq8 + (size_t)mBase * K_DIM + (size_t)kt * BK;
    const int8_t* gB = g_wq8 + (size_t)nBase * K_DIM + (size_t)kt * BK;
    #pragma unroll
    for (int j = 0; j < 4; ++j) {               // A: 1024 chunks of 16B
        int id = tid + 256 * j;
        int r = id >> 3, c = id & 7;
        uint32_t off = (uint32_t)(r * BK + c * 16);
        cp_async16(sA + SWZ128(off), gA + (size_t)r * K_DIM + c * 16);
    }
    #pragma unroll
    for (int j = 0; j < 8; ++j) {               // B: 2048 chunks of 16B
        int id = tid + 256 * j;
        int r = id >> 3, c = id & 7;
        uint32_t off = (uint32_t)(r * BK + c * 16);
        cp_async16(sB + SWZ128(off), gB + (size_t)r * K_DIM + c * 16);
    }
}

__global__ void __launch_bounds__(256, 1) bitlinear_gemm(float* __restrict__ out) {
    extern __shared__ __align__(1024) uint8_t smem[];
    const uint32_t sb = smem_u32(smem);

    const int tid  = threadIdx.x;
    const int lane = tid & 31;
    const int wid  = tid >> 5;
    const int warpM = wid & 1;       // 2 warps over M (64 rows each)
    const int warpN = wid >> 1;      // 4 warps over N (64 cols each)
    const int mBase = blockIdx.y * BM;
    const int nBase = blockIdx.x * BN;   // x = N tiles -> W stays L2-resident

    // A ldmatrix.x4 addressing (validated R2/R3)
    uint32_t aRow128[4], aRswz[4];
    #pragma unroll
    for (int mi = 0; mi < 4; ++mi) {
        int r = warpM * 64 + mi * 16 + (lane & 7) + ((lane >> 3) & 1) * 8;
        aRow128[mi] = (uint32_t)(r * BK);
        aRswz[mi]   = (uint32_t)(r & 7);
    }
    const uint32_t aHi = (uint32_t)(lane >> 4);        // 0/1 : +16B chunk

    // B ldmatrix.x4: one load covers TWO n8 tiles (validated R3)
    uint32_t bRow128[4], bRswz[4];
    #pragma unroll
    for (int p = 0; p < 4; ++p) {
        int r = warpN * 64 + p * 16 + (lane & 7) + ((lane >> 4) & 1) * 8;
        bRow128[p] = (uint32_t)(r * BK);
        bRswz[p]   = (uint32_t)(r & 7);
    }
    const uint32_t bHi = (uint32_t)((lane >> 3) & 1);  // 0/1 : +16B chunk

    int acc[4][8][4];
    #pragma unroll
    for (int mi = 0; mi < 4; ++mi)
        #pragma unroll
        for (int ni = 0; ni < 8; ++ni)
            #pragma unroll
            for (int j = 0; j < 4; ++j) acc[mi][ni][j] = 0;

    // Prologue: fill 2 stages
    load_stage(sb + 0 * STAGE_BYTES, 0, mBase, nBase, tid); cp_commit();
    load_stage(sb + 1 * STAGE_BYTES, 1, mBase, nBase, tid); cp_commit();

    // Double-buffered register fragments
    uint32_t aF[2][4][4], bF[2][8][2];

    int st = 0;
    for (int kt = 0; kt < KT; ++kt) {
        cp_wait<1>();
        __syncthreads();

        int st2 = st + 2; if (st2 >= STAGES) st2 -= STAGES;
        if (kt + 2 < KT)
            load_stage(sb + st2 * STAGE_BYTES, kt + 2, mBase, nBase, tid);
        cp_commit();   // uniform group accounting

        const uint32_t sA = sb + st * STAGE_BYTES;
        const uint32_t sB = sA + A_BYTES;

        // Preload ks=0 fragments into buffer 0
        {
            const uint32_t chA = aHi;          // ks=0
            const uint32_t chB = bHi;
            #pragma unroll
            for (int p = 0; p < 4; ++p) {
                uint32_t r4[4];
                ldsm_x4(r4, sB + bRow128[p] + (((chB) ^ bRswz[p]) << 4));
                bF[0][2 * p][0] = r4[0]; bF[0][2 * p][1] = r4[1];
                bF[0][2 * p + 1][0] = r4[2]; bF[0][2 * p + 1][1] = r4[3];
            }
            #pragma unroll
            for (int mi = 0; mi < 4; ++mi)
                ldsm_x4(aF[0][mi], sA + aRow128[mi] + (((chA) ^ aRswz[mi]) << 4));
        }

        #pragma unroll
        for (int ks = 0; ks < 4; ++ks) {
            const int cur = ks & 1;
            const int nxt = cur ^ 1;
            // Prefetch ks+1 fragments (overlaps with the 32 MMAs below)
            if (ks < 3) {
                const uint32_t chA = (uint32_t)((ks + 1) * 2) + aHi;
                const uint32_t chB = (uint32_t)((ks + 1) * 2) + bHi;
                #pragma unroll
                for (int p = 0; p < 4; ++p) {
                    uint32_t r4[4];
                    ldsm_x4(r4, sB + bRow128[p] + ((chB ^ bRswz[p]) << 4));
                    bF[nxt][2 * p][0] = r4[0]; bF[nxt][2 * p][1] = r4[1];
                    bF[nxt][2 * p + 1][0] = r4[2]; bF[nxt][2 * p + 1][1] = r4[3];
                }
                #pragma unroll
                for (int mi = 0; mi < 4; ++mi)
                    ldsm_x4(aF[nxt][mi], sA + aRow128[mi] + ((chA ^ aRswz[mi]) << 4));
            }
            #pragma unroll
            for (int mi = 0; mi < 4; ++mi)
                #pragma unroll
                for (int ni = 0; ni < 8; ++ni)
                    mma_s8(acc[mi][ni], aF[cur][mi], bF[cur][ni]);
        }

        if (++st == STAGES) st = 0;
    }

    // Epilogue: rescale + store (exact integer acc -> f32)
    const int g = lane >> 2;
    const int t4 = lane & 3;
    #pragma unroll
    for (int mi = 0; mi < 4; ++mi) {
        const int r0 = mBase + warpM * 64 + mi * 16 + g;
        const float as0 = g_ascale[r0];
        const float as1 = g_ascale[r0 + 8];
        float* o0 = out + (size_t)r0 * N_DIM;
        float* o1 = o0 + (size_t)8 * N_DIM;
        #pragma unroll
        for (int ni = 0; ni < 8; ++ni) {
            const int col = nBase + warpN * 64 + ni * 8 + 2 * t4;
            const float2 wv = *(const float2*)(g_wsa + col);
            float2 y0, y1;
            y0.x = (float)acc[mi][ni][0] * as0 * wv.x;
            y0.y = (float)acc[mi][ni][1] * as0 * wv.y;
            y1.x = (float)acc[mi][ni][2] * as1 * wv.x;
            y1.y = (float)acc[mi][ni][3] * as1 * wv.y;
            *(float2*)(o0 + col) = y0;
            *(float2*)(o1 + col) = y1;
        }
    }
}

// ---------------------------------------------------------------------------
// Launch
// ---------------------------------------------------------------------------
extern "C" void kernel_launch(void* const* d_in, const int* in_sizes, int n_in,
                              void* d_out, int out_size) {
    const float* x     = (const float*)d_in[0];
    const float* w     = (const float*)d_in[1];
    const float* alpha = (const float*)d_in[2];
    float* out = (float*)d_out;

    const int mrows = in_sizes[0] / K_DIM;   // 8192

    cudaFuncSetAttribute(bitlinear_gemm,
                         cudaFuncAttributeMaxDynamicSharedMemorySize, GEMM_SMEM);

    wquant_kernel<<<N_DIM, 256>>>(w, alpha);
    aquant_kernel<<<mrows, 256>>>(x);

    dim3 grid(N_DIM / BN, mrows / BM);
    bitlinear_gemm<<<grid, 256, GEMM_SMEM>>>(out);
}

// round 5
// speedup vs baseline: 1.0749x; 1.0749x over previous
#include <cuda_runtime.h>
#include <cuda_bf16.h>
#include <cstdint>

// ---------------------------------------------------------------------------
// BitLinear forward on base sm_100 (tcgen05 unavailable at this PTX target):
//   1) fused quant kernel: ternary weight quant + int8 activation quant
//   2) int8 GEMM via mma.sync.m16n8k32.s8 (exact integer accumulation)
//   3) fused float rescale epilogue
// M = 8192, N = 4096, K = 4096.
// R5: BK=256 / 2-stage pipeline (halves barrier+drain events), fused quant
//     pre-pass, fp32 weight-scale reduction.
// ---------------------------------------------------------------------------

#define K_DIM 4096
#define N_DIM 4096
#define M_ROWS_MAX 8192

#define BM 128
#define BN 256
#define BK 256              // int8 elements == bytes (2 x 128B sub-tiles)
#define STAGES 2
#define KT (K_DIM / BK)     // 16

#define A_SUB 16384                     // 128 x 128
#define B_SUB 32768                     // 256 x 128
#define A_BYTES (2 * A_SUB)             // 32768
#define B_BYTES (2 * B_SUB)             // 65536
#define STAGE_BYTES (A_BYTES + B_BYTES) // 98304
#define GEMM_SMEM (STAGES * STAGE_BYTES) // 196608

// Scratch (device globals; runtime allocation is forbidden)
__device__ int8_t g_aq8[(size_t)M_ROWS_MAX * K_DIM];   // 32 MB
__device__ int8_t g_wq8[(size_t)N_DIM * K_DIM];        // 16 MB
__device__ float  g_ascale[M_ROWS_MAX];                // max|x| + eps
__device__ float  g_wsa[N_DIM];                        // w_scale * alpha / 127

// ---------------------------------------------------------------------------
// PTX helpers (base-sm_100 legal: cp.async, ldmatrix, mma.sync)
// ---------------------------------------------------------------------------
__device__ __forceinline__ uint32_t smem_u32(const void* p) {
    uint32_t a;
    asm("{ .reg .u64 t; cvta.to.shared.u64 t, %1; cvt.u32.u64 %0, t; }"
        : "=r"(a) : "l"(p));
    return a;
}

__device__ __forceinline__ void cp_async16(uint32_t dst, const void* src) {
    asm volatile("cp.async.cg.shared.global [%0], [%1], 16;"
                 :: "r"(dst), "l"(src) : "memory");
}
__device__ __forceinline__ void cp_commit() {
    asm volatile("cp.async.commit_group;" ::: "memory");
}
template <int N>
__device__ __forceinline__ void cp_wait() {
    asm volatile("cp.async.wait_group %0;" :: "n"(N) : "memory");
}

__device__ __forceinline__ void ldsm_x4(uint32_t* r, uint32_t addr) {
    asm volatile("ldmatrix.sync.aligned.m8n8.x4.shared.b16 {%0,%1,%2,%3}, [%4];"
                 : "=r"(r[0]), "=r"(r[1]), "=r"(r[2]), "=r"(r[3]) : "r"(addr));
}

__device__ __forceinline__ void mma_s8(int* d, const uint32_t* a, const uint32_t* b) {
    asm volatile(
        "mma.sync.aligned.m16n8k32.row.col.s32.s8.s8.s32 "
        "{%0,%1,%2,%3}, {%4,%5,%6,%7}, {%8,%9}, {%0,%1,%2,%3};"
        : "+r"(d[0]), "+r"(d[1]), "+r"(d[2]), "+r"(d[3])
        : "r"(a[0]), "r"(a[1]), "r"(a[2]), "r"(a[3]), "r"(b[0]), "r"(b[1]));
}

// swizzle: 16B chunk within a 128B row XOR'ed by (row & 7)
#define SWZ128(x) ((x) ^ (((x) >> 3) & 0x70))

// ---------------------------------------------------------------------------
// Block reductions (fp32)
// ---------------------------------------------------------------------------
__device__ __forceinline__ float block_max(float v) {
    __shared__ float sh[8];
    #pragma unroll
    for (int o = 16; o; o >>= 1) v = fmaxf(v, __shfl_xor_sync(0xffffffffu, v, o));
    if ((threadIdx.x & 31) == 0) sh[threadIdx.x >> 5] = v;
    __syncthreads();
    if (threadIdx.x < 32) {
        float t = (threadIdx.x < 8) ? sh[threadIdx.x] : 0.0f;
        #pragma unroll
        for (int o = 4; o; o >>= 1) t = fmaxf(t, __shfl_xor_sync(0xffffffffu, t, o));
        if (threadIdx.x == 0) sh[0] = t;
    }
    __syncthreads();
    return sh[0];
}

__device__ __forceinline__ float block_sum_f(float v) {
    __shared__ float sh[8];
    #pragma unroll
    for (int o = 16; o; o >>= 1) v += __shfl_xor_sync(0xffffffffu, v, o);
    if ((threadIdx.x & 31) == 0) sh[threadIdx.x >> 5] = v;
    __syncthreads();
    if (threadIdx.x < 32) {
        float t = (threadIdx.x < 8) ? sh[threadIdx.x] : 0.0f;
        #pragma unroll
        for (int o = 4; o; o >>= 1) t += __shfl_xor_sync(0xffffffffu, t, o);
        if (threadIdx.x == 0) sh[0] = t;
    }
    __syncthreads();
    return sh[0];
}

// ---------------------------------------------------------------------------
// Fused quantization kernel.
//   blocks [0, N_DIM)           : weight rows   (ternary quant)
//   blocks [N_DIM, N_DIM+mrows) : activation rows (int8 quant)
// One block handles one row of 4096 floats.
// ---------------------------------------------------------------------------
__global__ void __launch_bounds__(256) quant_kernel(const float* __restrict__ w,
                                                    const float* __restrict__ alpha,
                                                    const float* __restrict__ x) {
    if ((int)blockIdx.x < N_DIM) {
        const int row = blockIdx.x;
        const float4* wr = (const float4*)(w + (size_t)row * K_DIM);
        float4 v[4];
        float acc = 0.0f;
        #pragma unroll
        for (int i = 0; i < 4; ++i) {
            v[i] = wr[threadIdx.x + 256 * i];
            acc += fabsf(v[i].x) + fabsf(v[i].y) + fabsf(v[i].z) + fabsf(v[i].w);
        }
        float total = block_sum_f(acc);
        float scale = total * (1.0f / 4096.0f) + 1e-8f;   // mean(|w|) + EPS
        if (threadIdx.x == 0)
            g_wsa[row] = scale * (alpha[row] * (1.0f / 127.0f));

        uint32_t* dst = (uint32_t*)(g_wq8 + (size_t)row * K_DIM);
        #pragma unroll
        for (int i = 0; i < 4; ++i) {
            float q[4] = {v[i].x, v[i].y, v[i].z, v[i].w};
            uint32_t p = 0;
            #pragma unroll
            for (int j = 0; j < 4; ++j) {
                float wn = __fdiv_rn(q[j], scale);
                float r = rintf(wn);                      // round-half-even like jnp
                r = fminf(fmaxf(r, -1.0f), 1.0f);         // clip AFTER round
                p |= ((uint32_t)((int)r & 0xff)) << (8 * j);
            }
            dst[threadIdx.x + 256 * i] = p;
        }
    } else {
        const int row = (int)blockIdx.x - N_DIM;
        const float4* xr = (const float4*)(x + (size_t)row * K_DIM);
        float4 v[4];
        float mx = 0.0f;
        #pragma unroll
        for (int i = 0; i < 4; ++i) {
            v[i] = xr[threadIdx.x + 256 * i];
            mx = fmaxf(mx, fmaxf(fmaxf(fabsf(v[i].x), fabsf(v[i].y)),
                                 fmaxf(fabsf(v[i].z), fabsf(v[i].w))));
        }
        mx = block_max(mx);
        float s = mx + 1e-8f;                              // a_scale (max is exact)
        if (threadIdx.x == 0) g_ascale[row] = s;

        uint32_t* dst = (uint32_t*)(g_aq8 + (size_t)row * K_DIM);
        #pragma unroll
        for (int i = 0; i < 4; ++i) {
            float q[4] = {v[i].x, v[i].y, v[i].z, v[i].w};
            uint32_t p = 0;
            #pragma unroll
            for (int j = 0; j < 4; ++j) {
                // EXACT op order of reference: (x / a_scale) * 127 ; clip ; round
                float t = __fdiv_rn(q[j], s) * 127.0f;
                t = fminf(fmaxf(t, -128.0f), 127.0f);
                t = rintf(t);
                p |= ((uint32_t)((int)t & 0xff)) << (8 * j);
            }
            dst[threadIdx.x + 256 * i] = p;
        }
    }
}

// ---------------------------------------------------------------------------
// int8 GEMM: out[m][n] = (sum_k aq[m][k]*wq[n][k]) * ascale[m] * wsa[n]
// CTA 128x256, warp 64x64, 2-stage cp.async pipeline with BK=256
// (two 128B-wide sub-tiles per stage), mma.sync.m16n8k32.s8.
// ---------------------------------------------------------------------------
__device__ __forceinline__ void load_stage(uint32_t sBase, int kt,
                                           int mBase, int nBase, int tid) {
    #pragma unroll
    for (int sub = 0; sub < 2; ++sub) {
        const uint32_t sA = sBase + sub * A_SUB;
        const uint32_t sB = sBase + A_BYTES + sub * B_SUB;
        const int8_t* gA = g_aq8 + (size_t)mBase * K_DIM + (size_t)kt * BK + sub * 128;
        const int8_t* gB = g_wq8 + (size_t)nBase * K_DIM + (size_t)kt * BK + sub * 128;
        #pragma unroll
        for (int j = 0; j < 4; ++j) {               // A sub: 1024 chunks of 16B
            int id = tid + 256 * j;
            int r = id >> 3, c = id & 7;
            uint32_t off = (uint32_t)(r * 128 + c * 16);
            cp_async16(sA + SWZ128(off), gA + (size_t)r * K_DIM + c * 16);
        }
        #pragma unroll
        for (int j = 0; j < 8; ++j) {               // B sub: 2048 chunks of 16B
            int id = tid + 256 * j;
            int r = id >> 3, c = id & 7;
            uint32_t off = (uint32_t)(r * 128 + c * 16);
            cp_async16(sB + SWZ128(off), gB + (size_t)r * K_DIM + c * 16);
        }
    }
}

__global__ void __launch_bounds__(256, 1) bitlinear_gemm(float* __restrict__ out) {
    extern __shared__ __align__(1024) uint8_t smem[];
    const uint32_t sb = smem_u32(smem);

    const int tid  = threadIdx.x;
    const int lane = tid & 31;
    const int wid  = tid >> 5;
    const int warpM = wid & 1;       // 2 warps over M (64 rows each)
    const int warpN = wid >> 1;      // 4 warps over N (64 cols each)
    const int mBase = blockIdx.y * BM;
    const int nBase = blockIdx.x * BN;   // x = N tiles -> W stays L2-resident

    // A ldmatrix.x4 addressing within a 128B-wide sub-tile (validated R2/R3)
    uint32_t aRow128[4], aRswz[4];
    #pragma unroll
    for (int mi = 0; mi < 4; ++mi) {
        int r = warpM * 64 + mi * 16 + (lane & 7) + ((lane >> 3) & 1) * 8;
        aRow128[mi] = (uint32_t)(r * 128);
        aRswz[mi]   = (uint32_t)(r & 7);
    }
    const uint32_t aHi = (uint32_t)(lane >> 4);        // 0/1 : +16B chunk

    // B ldmatrix.x4: one load covers TWO n8 tiles (validated R3)
    uint32_t bRow128[4], bRswz[4];
    #pragma unroll
    for (int p = 0; p < 4; ++p) {
        int r = warpN * 64 + p * 16 + (lane & 7) + ((lane >> 4) & 1) * 8;
        bRow128[p] = (uint32_t)(r * 128);
        bRswz[p]   = (uint32_t)(r & 7);
    }
    const uint32_t bHi = (uint32_t)((lane >> 3) & 1);  // 0/1 : +16B chunk

    int acc[4][8][4];
    #pragma unroll
    for (int mi = 0; mi < 4; ++mi)
        #pragma unroll
        for (int ni = 0; ni < 8; ++ni)
            #pragma unroll
            for (int j = 0; j < 4; ++j) acc[mi][ni][j] = 0;

    // Prologue: fill stage 0
    load_stage(sb, 0, mBase, nBase, tid);
    cp_commit();

    for (int kt = 0; kt < KT; ++kt) {
        cp_wait<0>();          // stage (kt&1) landed
        __syncthreads();       // ...and previous compute finished everywhere

        if (kt + 1 < KT) {     // overlap next-stage fill with this compute
            load_stage(sb + ((kt + 1) & 1) * STAGE_BYTES, kt + 1, mBase, nBase, tid);
            cp_commit();
        }

        const uint32_t stBase = sb + (kt & 1) * STAGE_BYTES;

        #pragma unroll
        for (int ks = 0; ks < 8; ++ks) {
            const uint32_t sA = stBase + (uint32_t)(ks >> 2) * A_SUB;
            const uint32_t sB = stBase + A_BYTES + (uint32_t)(ks >> 2) * B_SUB;
            uint32_t aF[4][4], bF[8][2];
            #pragma unroll
            for (int p = 0; p < 4; ++p) {
                uint32_t ch = (uint32_t)((ks & 3) * 2) + bHi;
                uint32_t r4[4];
                ldsm_x4(r4, sB + bRow128[p] + ((ch ^ bRswz[p]) << 4));
                bF[2 * p][0] = r4[0]; bF[2 * p][1] = r4[1];
                bF[2 * p + 1][0] = r4[2]; bF[2 * p + 1][1] = r4[3];
            }
            #pragma unroll
            for (int mi = 0; mi < 4; ++mi) {
                uint32_t ch = (uint32_t)((ks & 3) * 2) + aHi;
                ldsm_x4(aF[mi], sA + aRow128[mi] + ((ch ^ aRswz[mi]) << 4));
            }
            #pragma unroll
            for (int mi = 0; mi < 4; ++mi)
                #pragma unroll
                for (int ni = 0; ni < 8; ++ni)
                    mma_s8(acc[mi][ni], aF[mi], bF[ni]);
        }
    }

    // Epilogue: rescale + store (exact integer acc -> f32)
    const int g = lane >> 2;
    const int t4 = lane & 3;
    #pragma unroll
    for (int mi = 0; mi < 4; ++mi) {
        const int r0 = mBase + warpM * 64 + mi * 16 + g;
        const float as0 = g_ascale[r0];
        const float as1 = g_ascale[r0 + 8];
        float* o0 = out + (size_t)r0 * N_DIM;
        float* o1 = o0 + (size_t)8 * N_DIM;
        #pragma unroll
        for (int ni = 0; ni < 8; ++ni) {
            const int col = nBase + warpN * 64 + ni * 8 + 2 * t4;
            const float2 wv = *(const float2*)(g_wsa + col);
            float2 y0, y1;
            y0.x = (float)acc[mi][ni][0] * as0 * wv.x;
            y0.y = (float)acc[mi][ni][1] * as0 * wv.y;
            y1.x = (float)acc[mi][ni][2] * as1 * wv.x;
            y1.y = (float)acc[mi][ni][3] * as1 * wv.y;
            *(float2*)(o0 + col) = y0;
            *(float2*)(o1 + col) = y1;
        }
    }
}

// ---------------------------------------------------------------------------
// Launch
// ---------------------------------------------------------------------------
extern "C" void kernel_launch(void* const* d_in, const int* in_sizes, int n_in,
                              void* d_out, int out_size) {
    const float* x     = (const float*)d_in[0];
    const float* w     = (const float*)d_in[1];
    const float* alpha = (const float*)d_in[2];
    float* out = (float*)d_out;

    const int mrows = in_sizes[0] / K_DIM;   // 8192

    cudaFuncSetAttribute(bitlinear_gemm,
                         cudaFuncAttributeMaxDynamicSharedMemorySize, GEMM_SMEM);

    quant_kernel<<<N_DIM + mrows, 256>>>(w, alpha, x);

    dim3 grid(N_DIM / BN, mrows / BM);
    bitlinear_gemm<<<grid, 256, GEMM_SMEM>>>(out);
}

// round 6
// speedup vs baseline: 1.1068x; 1.0297x over previous
#include <cuda_runtime.h>
#include <cuda_bf16.h>
#include <cstdint>

// ---------------------------------------------------------------------------
// BitLinear forward on base sm_100 (tcgen05 unavailable at this PTX target):
//   1) fused quant kernel: ternary weight quant + int8 activation quant
//   2) int8 GEMM via mma.sync.m16n8k32.s8 (exact integer accumulation)
//   3) fused float rescale epilogue
// M = 8192, N = 4096, K = 4096.
// R6: 2 CTAs/SM (128x128 tile, 96KB smem, <=128 regs) so co-resident CTAs
//     cover each other's barrier/drain gaps -> feed the tensor pipe.
// ---------------------------------------------------------------------------

#define K_DIM 4096
#define N_DIM 4096
#define M_ROWS_MAX 8192

#define BM 128
#define BN 128
#define BK 128              // int8 elements == bytes
#define STAGES 3
#define KT (K_DIM / BK)     // 32

#define A_BYTES (BM * BK)               // 16384
#define B_BYTES (BN * BK)               // 16384
#define STAGE_BYTES (A_BYTES + B_BYTES) // 32768
#define GEMM_SMEM (STAGES * STAGE_BYTES) // 98304 (2 CTAs fit in 227KB)

// Scratch (device globals; runtime allocation is forbidden)
__device__ int8_t g_aq8[(size_t)M_ROWS_MAX * K_DIM];   // 32 MB
__device__ int8_t g_wq8[(size_t)N_DIM * K_DIM];        // 16 MB
__device__ float  g_ascale[M_ROWS_MAX];                // max|x| + eps
__device__ float  g_wsa[N_DIM];                        // w_scale * alpha / 127

// ---------------------------------------------------------------------------
// PTX helpers (base-sm_100 legal: cp.async, ldmatrix, mma.sync)
// ---------------------------------------------------------------------------
__device__ __forceinline__ uint32_t smem_u32(const void* p) {
    uint32_t a;
    asm("{ .reg .u64 t; cvta.to.shared.u64 t, %1; cvt.u32.u64 %0, t; }"
        : "=r"(a) : "l"(p));
    return a;
}

__device__ __forceinline__ void cp_async16(uint32_t dst, const void* src) {
    asm volatile("cp.async.cg.shared.global [%0], [%1], 16;"
                 :: "r"(dst), "l"(src) : "memory");
}
__device__ __forceinline__ void cp_commit() {
    asm volatile("cp.async.commit_group;" ::: "memory");
}
template <int N>
__device__ __forceinline__ void cp_wait() {
    asm volatile("cp.async.wait_group %0;" :: "n"(N) : "memory");
}

__device__ __forceinline__ void ldsm_x4(uint32_t* r, uint32_t addr) {
    asm volatile("ldmatrix.sync.aligned.m8n8.x4.shared.b16 {%0,%1,%2,%3}, [%4];"
                 : "=r"(r[0]), "=r"(r[1]), "=r"(r[2]), "=r"(r[3]) : "r"(addr));
}

__device__ __forceinline__ void mma_s8(int* d, const uint32_t* a, const uint32_t* b) {
    asm volatile(
        "mma.sync.aligned.m16n8k32.row.col.s32.s8.s8.s32 "
        "{%0,%1,%2,%3}, {%4,%5,%6,%7}, {%8,%9}, {%0,%1,%2,%3};"
        : "+r"(d[0]), "+r"(d[1]), "+r"(d[2]), "+r"(d[3])
        : "r"(a[0]), "r"(a[1]), "r"(a[2]), "r"(a[3]), "r"(b[0]), "r"(b[1]));
}

// swizzle: 16B chunk within a 128B row XOR'ed by (row & 7)
#define SWZ128(x) ((x) ^ (((x) >> 3) & 0x70))

// ---------------------------------------------------------------------------
// Block reductions (fp32)
// ---------------------------------------------------------------------------
__device__ __forceinline__ float block_max(float v) {
    __shared__ float sh[8];
    #pragma unroll
    for (int o = 16; o; o >>= 1) v = fmaxf(v, __shfl_xor_sync(0xffffffffu, v, o));
    if ((threadIdx.x & 31) == 0) sh[threadIdx.x >> 5] = v;
    __syncthreads();
    if (threadIdx.x < 32) {
        float t = (threadIdx.x < 8) ? sh[threadIdx.x] : 0.0f;
        #pragma unroll
        for (int o = 4; o; o >>= 1) t = fmaxf(t, __shfl_xor_sync(0xffffffffu, t, o));
        if (threadIdx.x == 0) sh[0] = t;
    }
    __syncthreads();
    return sh[0];
}

__device__ __forceinline__ float block_sum_f(float v) {
    __shared__ float sh[8];
    #pragma unroll
    for (int o = 16; o; o >>= 1) v += __shfl_xor_sync(0xffffffffu, v, o);
    if ((threadIdx.x & 31) == 0) sh[threadIdx.x >> 5] = v;
    __syncthreads();
    if (threadIdx.x < 32) {
        float t = (threadIdx.x < 8) ? sh[threadIdx.x] : 0.0f;
        #pragma unroll
        for (int o = 4; o; o >>= 1) t += __shfl_xor_sync(0xffffffffu, t, o);
        if (threadIdx.x == 0) sh[0] = t;
    }
    __syncthreads();
    return sh[0];
}

// ---------------------------------------------------------------------------
// Fused quantization kernel.
//   blocks [0, N_DIM)           : weight rows   (ternary quant)
//   blocks [N_DIM, N_DIM+mrows) : activation rows (int8 quant)
// ---------------------------------------------------------------------------
__global__ void __launch_bounds__(256) quant_kernel(const float* __restrict__ w,
                                                    const float* __restrict__ alpha,
                                                    const float* __restrict__ x) {
    if ((int)blockIdx.x < N_DIM) {
        const int row = blockIdx.x;
        const float4* wr = (const float4*)(w + (size_t)row * K_DIM);
        float4 v[4];
        float acc = 0.0f;
        #pragma unroll
        for (int i = 0; i < 4; ++i) {
            v[i] = wr[threadIdx.x + 256 * i];
            acc += fabsf(v[i].x) + fabsf(v[i].y) + fabsf(v[i].z) + fabsf(v[i].w);
        }
        float total = block_sum_f(acc);
        float scale = total * (1.0f / 4096.0f) + 1e-8f;   // mean(|w|) + EPS
        if (threadIdx.x == 0)
            g_wsa[row] = scale * (alpha[row] * (1.0f / 127.0f));

        uint32_t* dst = (uint32_t*)(g_wq8 + (size_t)row * K_DIM);
        #pragma unroll
        for (int i = 0; i < 4; ++i) {
            float q[4] = {v[i].x, v[i].y, v[i].z, v[i].w};
            uint32_t p = 0;
            #pragma unroll
            for (int j = 0; j < 4; ++j) {
                float wn = __fdiv_rn(q[j], scale);
                float r = rintf(wn);                      // round-half-even like jnp
                r = fminf(fmaxf(r, -1.0f), 1.0f);         // clip AFTER round
                p |= ((uint32_t)((int)r & 0xff)) << (8 * j);
            }
            dst[threadIdx.x + 256 * i] = p;
        }
    } else {
        const int row = (int)blockIdx.x - N_DIM;
        const float4* xr = (const float4*)(x + (size_t)row * K_DIM);
        float4 v[4];
        float mx = 0.0f;
        #pragma unroll
        for (int i = 0; i < 4; ++i) {
            v[i] = xr[threadIdx.x + 256 * i];
            mx = fmaxf(mx, fmaxf(fmaxf(fabsf(v[i].x), fabsf(v[i].y)),
                                 fmaxf(fabsf(v[i].z), fabsf(v[i].w))));
        }
        mx = block_max(mx);
        float s = mx + 1e-8f;                              // a_scale (max is exact)
        if (threadIdx.x == 0) g_ascale[row] = s;

        uint32_t* dst = (uint32_t*)(g_aq8 + (size_t)row * K_DIM);
        #pragma unroll
        for (int i = 0; i < 4; ++i) {
            float q[4] = {v[i].x, v[i].y, v[i].z, v[i].w};
            uint32_t p = 0;
            #pragma unroll
            for (int j = 0; j < 4; ++j) {
                // EXACT op order of reference: (x / a_scale) * 127 ; clip ; round
                float t = __fdiv_rn(q[j], s) * 127.0f;
                t = fminf(fmaxf(t, -128.0f), 127.0f);
                t = rintf(t);
                p |= ((uint32_t)((int)t & 0xff)) << (8 * j);
            }
            dst[threadIdx.x + 256 * i] = p;
        }
    }
}

// ---------------------------------------------------------------------------
// int8 GEMM: out[m][n] = (sum_k aq[m][k]*wq[n][k]) * ascale[m] * wsa[n]
// CTA 128x128, warp 64x32 (2x4 warps), 3-stage cp.async pipeline,
// 2 CTAs per SM for cross-CTA latency hiding.
// ---------------------------------------------------------------------------
__device__ __forceinline__ void load_stage(uint32_t sBase, int kt,
                                           int mBase, int nBase, int tid) {
    const uint32_t sA = sBase;
    const uint32_t sB = sBase + A_BYTES;
    const int8_t* gA = g_aq8 + (size_t)mBase * K_DIM + (size_t)kt * BK;
    const int8_t* gB = g_wq8 + (size_t)nBase * K_DIM + (size_t)kt * BK;
    #pragma unroll
    for (int j = 0; j < 4; ++j) {               // A: 1024 chunks of 16B
        int id = tid + 256 * j;
        int r = id >> 3, c = id & 7;
        uint32_t off = (uint32_t)(r * BK + c * 16);
        cp_async16(sA + SWZ128(off), gA + (size_t)r * K_DIM + c * 16);
    }
    #pragma unroll
    for (int j = 0; j < 4; ++j) {               // B: 1024 chunks of 16B
        int id = tid + 256 * j;
        int r = id >> 3, c = id & 7;
        uint32_t off = (uint32_t)(r * BK + c * 16);
        cp_async16(sB + SWZ128(off), gB + (size_t)r * K_DIM + c * 16);
    }
}

__global__ void __launch_bounds__(256, 2) bitlinear_gemm(float* __restrict__ out) {
    extern __shared__ __align__(1024) uint8_t smem[];
    const uint32_t sb = smem_u32(smem);

    const int tid  = threadIdx.x;
    const int lane = tid & 31;
    const int wid  = tid >> 5;
    const int warpM = wid & 1;       // 2 warps over M (64 rows each)
    const int warpN = wid >> 1;      // 4 warps over N (32 cols each)
    const int mBase = blockIdx.y * BM;
    const int nBase = blockIdx.x * BN;   // x = N tiles -> W stays L2-resident

    // A ldmatrix.x4 addressing (validated R2/R3)
    uint32_t aRow128[4], aRswz[4];
    #pragma unroll
    for (int mi = 0; mi < 4; ++mi) {
        int r = warpM * 64 + mi * 16 + (lane & 7) + ((lane >> 3) & 1) * 8;
        aRow128[mi] = (uint32_t)(r * BK);
        aRswz[mi]   = (uint32_t)(r & 7);
    }
    const uint32_t aHi = (uint32_t)(lane >> 4);        // 0/1 : +16B chunk

    // B ldmatrix.x4: one load covers TWO n8 tiles (validated R3); warp has
    // 32 N-cols -> 2 pair-loads per ks.
    uint32_t bRow128[2], bRswz[2];
    #pragma unroll
    for (int p = 0; p < 2; ++p) {
        int r = warpN * 32 + p * 16 + (lane & 7) + ((lane >> 4) & 1) * 8;
        bRow128[p] = (uint32_t)(r * BK);
        bRswz[p]   = (uint32_t)(r & 7);
    }
    const uint32_t bHi = (uint32_t)((lane >> 3) & 1);  // 0/1 : +16B chunk

    int acc[4][4][4];
    #pragma unroll
    for (int mi = 0; mi < 4; ++mi)
        #pragma unroll
        for (int ni = 0; ni < 4; ++ni)
            #pragma unroll
            for (int j = 0; j < 4; ++j) acc[mi][ni][j] = 0;

    // Prologue: fill 2 stages
    load_stage(sb + 0 * STAGE_BYTES, 0, mBase, nBase, tid); cp_commit();
    load_stage(sb + 1 * STAGE_BYTES, 1, mBase, nBase, tid); cp_commit();

    int st = 0;
    for (int kt = 0; kt < KT; ++kt) {
        cp_wait<1>();
        __syncthreads();

        int st2 = st + 2; if (st2 >= STAGES) st2 -= STAGES;
        if (kt + 2 < KT)
            load_stage(sb + st2 * STAGE_BYTES, kt + 2, mBase, nBase, tid);
        cp_commit();   // uniform group accounting

        const uint32_t sA = sb + st * STAGE_BYTES;
        const uint32_t sB = sA + A_BYTES;

        #pragma unroll
        for (int ks = 0; ks < 4; ++ks) {
            uint32_t aF[4][4], bF[4][2];
            #pragma unroll
            for (int p = 0; p < 2; ++p) {
                uint32_t ch = (uint32_t)(ks * 2) + bHi;
                uint32_t r4[4];
                ldsm_x4(r4, sB + bRow128[p] + ((ch ^ bRswz[p]) << 4));
                bF[2 * p][0] = r4[0]; bF[2 * p][1] = r4[1];
                bF[2 * p + 1][0] = r4[2]; bF[2 * p + 1][1] = r4[3];
            }
            #pragma unroll
            for (int mi = 0; mi < 4; ++mi) {
                uint32_t ch = (uint32_t)(ks * 2) + aHi;
                ldsm_x4(aF[mi], sA + aRow128[mi] + ((ch ^ aRswz[mi]) << 4));
            }
            #pragma unroll
            for (int mi = 0; mi < 4; ++mi)
                #pragma unroll
                for (int ni = 0; ni < 4; ++ni)
                    mma_s8(acc[mi][ni], aF[mi], bF[ni]);
        }

        if (++st == STAGES) st = 0;
    }

    // Epilogue: rescale + store (exact integer acc -> f32)
    const int g = lane >> 2;
    const int t4 = lane & 3;
    #pragma unroll
    for (int mi = 0; mi < 4; ++mi) {
        const int r0 = mBase + warpM * 64 + mi * 16 + g;
        const float as0 = g_ascale[r0];
        const float as1 = g_ascale[r0 + 8];
        float* o0 = out + (size_t)r0 * N_DIM;
        float* o1 = o0 + (size_t)8 * N_DIM;
        #pragma unroll
        for (int ni = 0; ni < 4; ++ni) {
            const int col = nBase + warpN * 32 + ni * 8 + 2 * t4;
            const float2 wv = *(const float2*)(g_wsa + col);
            float2 y0, y1;
            y0.x = (float)acc[mi][ni][0] * as0 * wv.x;
            y0.y = (float)acc[mi][ni][1] * as0 * wv.y;
            y1.x = (float)acc[mi][ni][2] * as1 * wv.x;
            y1.y = (float)acc[mi][ni][3] * as1 * wv.y;
            *(float2*)(o0 + col) = y0;
            *(float2*)(o1 + col) = y1;
        }
    }
}

// ---------------------------------------------------------------------------
// Launch
// ---------------------------------------------------------------------------
extern "C" void kernel_launch(void* const* d_in, const int* in_sizes, int n_in,
                              void* d_out, int out_size) {
    const float* x     = (const float*)d_in[0];
    const float* w     = (const float*)d_in[1];
    const float* alpha = (const float*)d_in[2];
    float* out = (float*)d_out;

    const int mrows = in_sizes[0] / K_DIM;   // 8192

    cudaFuncSetAttribute(bitlinear_gemm,
                         cudaFuncAttributeMaxDynamicSharedMemorySize, GEMM_SMEM);

    quant_kernel<<<N_DIM + mrows, 256>>>(w, alpha, x);

    dim3 grid(N_DIM / BN, mrows / BM);
    bitlinear_gemm<<<grid, 256, GEMM_SMEM>>>(out);
}

// round 7
// speedup vs baseline: 1.1263x; 1.0177x over previous
#include <cuda_runtime.h>
#include <cuda_bf16.h>
#include <cstdint>

// ---------------------------------------------------------------------------
// BitLinear forward on base sm_100 (tcgen05 unavailable at this PTX target):
//   1) fused quant kernel: ternary weight quant + int8 activation quant
//   2) int8 GEMM via mma.sync.m16n8k32.s8 (exact integer accumulation)
//   3) fused float rescale epilogue
// M = 8192, N = 4096, K = 4096.
// R7: 128-thread CTAs (4 warps, warp tile 64x64) x 2 CTAs/SM.
//     64x64 warp tiles cut SMEM bytes/MAC by 34%; two independent barrier
//     domains per SM keep the tensor pipe covered.
// ---------------------------------------------------------------------------

#define K_DIM 4096
#define N_DIM 4096
#define M_ROWS_MAX 8192

#define BM 128
#define BN 128
#define BK 128              // int8 elements == bytes
#define STAGES 3
#define KT (K_DIM / BK)     // 32
#define CTA_THREADS 128

#define A_BYTES (BM * BK)               // 16384
#define B_BYTES (BN * BK)               // 16384
#define STAGE_BYTES (A_BYTES + B_BYTES) // 32768
#define GEMM_SMEM (STAGES * STAGE_BYTES) // 98304 per CTA, 2 CTAs/SM

// Scratch (device globals; runtime allocation is forbidden)
__device__ int8_t g_aq8[(size_t)M_ROWS_MAX * K_DIM];   // 32 MB
__device__ int8_t g_wq8[(size_t)N_DIM * K_DIM];        // 16 MB
__device__ float  g_ascale[M_ROWS_MAX];                // max|x| + eps
__device__ float  g_wsa[N_DIM];                        // w_scale * alpha / 127

// ---------------------------------------------------------------------------
// PTX helpers (base-sm_100 legal: cp.async, ldmatrix, mma.sync)
// ---------------------------------------------------------------------------
__device__ __forceinline__ uint32_t smem_u32(const void* p) {
    uint32_t a;
    asm("{ .reg .u64 t; cvta.to.shared.u64 t, %1; cvt.u32.u64 %0, t; }"
        : "=r"(a) : "l"(p));
    return a;
}

__device__ __forceinline__ void cp_async16(uint32_t dst, const void* src) {
    asm volatile("cp.async.cg.shared.global [%0], [%1], 16;"
                 :: "r"(dst), "l"(src) : "memory");
}
__device__ __forceinline__ void cp_commit() {
    asm volatile("cp.async.commit_group;" ::: "memory");
}
template <int N>
__device__ __forceinline__ void cp_wait() {
    asm volatile("cp.async.wait_group %0;" :: "n"(N) : "memory");
}

__device__ __forceinline__ void ldsm_x4(uint32_t* r, uint32_t addr) {
    asm volatile("ldmatrix.sync.aligned.m8n8.x4.shared.b16 {%0,%1,%2,%3}, [%4];"
                 : "=r"(r[0]), "=r"(r[1]), "=r"(r[2]), "=r"(r[3]) : "r"(addr));
}

__device__ __forceinline__ void mma_s8(int* d, const uint32_t* a, const uint32_t* b) {
    asm volatile(
        "mma.sync.aligned.m16n8k32.row.col.s32.s8.s8.s32 "
        "{%0,%1,%2,%3}, {%4,%5,%6,%7}, {%8,%9}, {%0,%1,%2,%3};"
        : "+r"(d[0]), "+r"(d[1]), "+r"(d[2]), "+r"(d[3])
        : "r"(a[0]), "r"(a[1]), "r"(a[2]), "r"(a[3]), "r"(b[0]), "r"(b[1]));
}

// swizzle: 16B chunk within a 128B row XOR'ed by (row & 7)
#define SWZ128(x) ((x) ^ (((x) >> 3) & 0x70))

// ---------------------------------------------------------------------------
// Block reductions (fp32), 256-thread quant blocks
// ---------------------------------------------------------------------------
__device__ __forceinline__ float block_max(float v) {
    __shared__ float sh[8];
    #pragma unroll
    for (int o = 16; o; o >>= 1) v = fmaxf(v, __shfl_xor_sync(0xffffffffu, v, o));
    if ((threadIdx.x & 31) == 0) sh[threadIdx.x >> 5] = v;
    __syncthreads();
    if (threadIdx.x < 32) {
        float t = (threadIdx.x < 8) ? sh[threadIdx.x] : 0.0f;
        #pragma unroll
        for (int o = 4; o; o >>= 1) t = fmaxf(t, __shfl_xor_sync(0xffffffffu, t, o));
        if (threadIdx.x == 0) sh[0] = t;
    }
    __syncthreads();
    return sh[0];
}

__device__ __forceinline__ float block_sum_f(float v) {
    __shared__ float sh[8];
    #pragma unroll
    for (int o = 16; o; o >>= 1) v += __shfl_xor_sync(0xffffffffu, v, o);
    if ((threadIdx.x & 31) == 0) sh[threadIdx.x >> 5] = v;
    __syncthreads();
    if (threadIdx.x < 32) {
        float t = (threadIdx.x < 8) ? sh[threadIdx.x] : 0.0f;
        #pragma unroll
        for (int o = 4; o; o >>= 1) t += __shfl_xor_sync(0xffffffffu, t, o);
        if (threadIdx.x == 0) sh[0] = t;
    }
    __syncthreads();
    return sh[0];
}

// ---------------------------------------------------------------------------
// Fused quantization kernel.
//   blocks [0, N_DIM)           : weight rows   (ternary quant)
//   blocks [N_DIM, N_DIM+mrows) : activation rows (int8 quant)
// ---------------------------------------------------------------------------
__global__ void __launch_bounds__(256) quant_kernel(const float* __restrict__ w,
                                                    const float* __restrict__ alpha,
                                                    const float* __restrict__ x) {
    if ((int)blockIdx.x < N_DIM) {
        const int row = blockIdx.x;
        const float4* wr = (const float4*)(w + (size_t)row * K_DIM);
        float4 v[4];
        float acc = 0.0f;
        #pragma unroll
        for (int i = 0; i < 4; ++i) {
            v[i] = wr[threadIdx.x + 256 * i];
            acc += fabsf(v[i].x) + fabsf(v[i].y) + fabsf(v[i].z) + fabsf(v[i].w);
        }
        float total = block_sum_f(acc);
        float scale = total * (1.0f / 4096.0f) + 1e-8f;   // mean(|w|) + EPS
        if (threadIdx.x == 0)
            g_wsa[row] = scale * (alpha[row] * (1.0f / 127.0f));

        uint32_t* dst = (uint32_t*)(g_wq8 + (size_t)row * K_DIM);
        #pragma unroll
        for (int i = 0; i < 4; ++i) {
            float q[4] = {v[i].x, v[i].y, v[i].z, v[i].w};
            uint32_t p = 0;
            #pragma unroll
            for (int j = 0; j < 4; ++j) {
                float wn = __fdiv_rn(q[j], scale);
                float r = rintf(wn);                      // round-half-even like jnp
                r = fminf(fmaxf(r, -1.0f), 1.0f);         // clip AFTER round
                p |= ((uint32_t)((int)r & 0xff)) << (8 * j);
            }
            dst[threadIdx.x + 256 * i] = p;
        }
    } else {
        const int row = (int)blockIdx.x - N_DIM;
        const float4* xr = (const float4*)(x + (size_t)row * K_DIM);
        float4 v[4];
        float mx = 0.0f;
        #pragma unroll
        for (int i = 0; i < 4; ++i) {
            v[i] = xr[threadIdx.x + 256 * i];
            mx = fmaxf(mx, fmaxf(fmaxf(fabsf(v[i].x), fabsf(v[i].y)),
                                 fmaxf(fabsf(v[i].z), fabsf(v[i].w))));
        }
        mx = block_max(mx);
        float s = mx + 1e-8f;                              // a_scale (max is exact)
        if (threadIdx.x == 0) g_ascale[row] = s;

        uint32_t* dst = (uint32_t*)(g_aq8 + (size_t)row * K_DIM);
        #pragma unroll
        for (int i = 0; i < 4; ++i) {
            float q[4] = {v[i].x, v[i].y, v[i].z, v[i].w};
            uint32_t p = 0;
            #pragma unroll
            for (int j = 0; j < 4; ++j) {
                // EXACT op order of reference: (x / a_scale) * 127 ; clip ; round
                float t = __fdiv_rn(q[j], s) * 127.0f;
                t = fminf(fmaxf(t, -128.0f), 127.0f);
                t = rintf(t);
                p |= ((uint32_t)((int)t & 0xff)) << (8 * j);
            }
            dst[threadIdx.x + 256 * i] = p;
        }
    }
}

// ---------------------------------------------------------------------------
// int8 GEMM: out[m][n] = (sum_k aq[m][k]*wq[n][k]) * ascale[m] * wsa[n]
// CTA 128x128 with 128 threads (4 warps, 2x2 grid, warp tile 64x64),
// 3-stage cp.async pipeline, 2 CTAs/SM.
// ---------------------------------------------------------------------------
__device__ __forceinline__ void load_stage(uint32_t sBase, int kt,
                                           int mBase, int nBase, int tid) {
    const uint32_t sA = sBase;
    const uint32_t sB = sBase + A_BYTES;
    const int8_t* gA = g_aq8 + (size_t)mBase * K_DIM + (size_t)kt * BK;
    const int8_t* gB = g_wq8 + (size_t)nBase * K_DIM + (size_t)kt * BK;
    #pragma unroll
    for (int j = 0; j < 8; ++j) {               // A: 1024 chunks of 16B
        int id = tid + CTA_THREADS * j;
        int r = id >> 3, c = id & 7;
        uint32_t off = (uint32_t)(r * BK + c * 16);
        cp_async16(sA + SWZ128(off), gA + (size_t)r * K_DIM + c * 16);
    }
    #pragma unroll
    for (int j = 0; j < 8; ++j) {               // B: 1024 chunks of 16B
        int id = tid + CTA_THREADS * j;
        int r = id >> 3, c = id & 7;
        uint32_t off = (uint32_t)(r * BK + c * 16);
        cp_async16(sB + SWZ128(off), gB + (size_t)r * K_DIM + c * 16);
    }
}

__global__ void __launch_bounds__(CTA_THREADS, 2) bitlinear_gemm(float* __restrict__ out) {
    extern __shared__ __align__(1024) uint8_t smem[];
    const uint32_t sb = smem_u32(smem);

    const int tid  = threadIdx.x;
    const int lane = tid & 31;
    const int wid  = tid >> 5;
    const int warpM = wid & 1;       // 2 warps over M (64 rows each)
    const int warpN = wid >> 1;      // 2 warps over N (64 cols each)
    const int mBase = blockIdx.y * BM;
    const int nBase = blockIdx.x * BN;   // x = N tiles -> W stays L2-resident

    // A ldmatrix.x4 addressing (validated R2/R3)
    uint32_t aRow128[4], aRswz[4];
    #pragma unroll
    for (int mi = 0; mi < 4; ++mi) {
        int r = warpM * 64 + mi * 16 + (lane & 7) + ((lane >> 3) & 1) * 8;
        aRow128[mi] = (uint32_t)(r * BK);
        aRswz[mi]   = (uint32_t)(r & 7);
    }
    const uint32_t aHi = (uint32_t)(lane >> 4);        // 0/1 : +16B chunk

    // B ldmatrix.x4: one load covers TWO n8 tiles (validated R3);
    // warp has 64 N-cols -> 4 pair-loads per ks.
    uint32_t bRow128[4], bRswz[4];
    #pragma unroll
    for (int p = 0; p < 4; ++p) {
        int r = warpN * 64 + p * 16 + (lane & 7) + ((lane >> 4) & 1) * 8;
        bRow128[p] = (uint32_t)(r * BK);
        bRswz[p]   = (uint32_t)(r & 7);
    }
    const uint32_t bHi = (uint32_t)((lane >> 3) & 1);  // 0/1 : +16B chunk

    int acc[4][8][4];
    #pragma unroll
    for (int mi = 0; mi < 4; ++mi)
        #pragma unroll
        for (int ni = 0; ni < 8; ++ni)
            #pragma unroll
            for (int j = 0; j < 4; ++j) acc[mi][ni][j] = 0;

    // Prologue: fill 2 stages
    load_stage(sb + 0 * STAGE_BYTES, 0, mBase, nBase, tid); cp_commit();
    load_stage(sb + 1 * STAGE_BYTES, 1, mBase, nBase, tid); cp_commit();

    int st = 0;
    for (int kt = 0; kt < KT; ++kt) {
        cp_wait<1>();
        __syncthreads();

        int st2 = st + 2; if (st2 >= STAGES) st2 -= STAGES;
        if (kt + 2 < KT)
            load_stage(sb + st2 * STAGE_BYTES, kt + 2, mBase, nBase, tid);
        cp_commit();   // uniform group accounting

        const uint32_t sA = sb + st * STAGE_BYTES;
        const uint32_t sB = sA + A_BYTES;

        #pragma unroll
        for (int ks = 0; ks < 4; ++ks) {
            uint32_t aF[4][4], bF[8][2];
            #pragma unroll
            for (int p = 0; p < 4; ++p) {
                uint32_t ch = (uint32_t)(ks * 2) + bHi;
                uint32_t r4[4];
                ldsm_x4(r4, sB + bRow128[p] + ((ch ^ bRswz[p]) << 4));
                bF[2 * p][0] = r4[0]; bF[2 * p][1] = r4[1];
                bF[2 * p + 1][0] = r4[2]; bF[2 * p + 1][1] = r4[3];
            }
            #pragma unroll
            for (int mi = 0; mi < 4; ++mi) {
                uint32_t ch = (uint32_t)(ks * 2) + aHi;
                ldsm_x4(aF[mi], sA + aRow128[mi] + ((ch ^ aRswz[mi]) << 4));
            }
            #pragma unroll
            for (int mi = 0; mi < 4; ++mi)
                #pragma unroll
                for (int ni = 0; ni < 8; ++ni)
                    mma_s8(acc[mi][ni], aF[mi], bF[ni]);
        }

        if (++st == STAGES) st = 0;
    }

    // Epilogue: rescale + store (exact integer acc -> f32)
    const int g = lane >> 2;
    const int t4 = lane & 3;
    #pragma unroll
    for (int mi = 0; mi < 4; ++mi) {
        const int r0 = mBase + warpM * 64 + mi * 16 + g;
        const float as0 = g_ascale[r0];
        const float as1 = g_ascale[r0 + 8];
        float* o0 = out + (size_t)r0 * N_DIM;
        float* o1 = o0 + (size_t)8 * N_DIM;
        #pragma unroll
        for (int ni = 0; ni < 8; ++ni) {
            const int col = nBase + warpN * 64 + ni * 8 + 2 * t4;
            const float2 wv = *(const float2*)(g_wsa + col);
            float2 y0, y1;
            y0.x = (float)acc[mi][ni][0] * as0 * wv.x;
            y0.y = (float)acc[mi][ni][1] * as0 * wv.y;
            y1.x = (float)acc[mi][ni][2] * as1 * wv.x;
            y1.y = (float)acc[mi][ni][3] * as1 * wv.y;
            *(float2*)(o0 + col) = y0;
            *(float2*)(o1 + col) = y1;
        }
    }
}

// ---------------------------------------------------------------------------
// Launch
// ---------------------------------------------------------------------------
extern "C" void kernel_launch(void* const* d_in, const int* in_sizes, int n_in,
                              void* d_out, int out_size) {
    const float* x     = (const float*)d_in[0];
    const float* w     = (const float*)d_in[1];
    const float* alpha = (const float*)d_in[2];
    float* out = (float*)d_out;

    const int mrows = in_sizes[0] / K_DIM;   // 8192

    cudaFuncSetAttribute(bitlinear_gemm,
                         cudaFuncAttributeMaxDynamicSharedMemorySize, GEMM_SMEM);

    quant_kernel<<<N_DIM + mrows, 256>>>(w, alpha, x);

    dim3 grid(N_DIM / BN, mrows / BM);
    bitlinear_gemm<<<grid, CTA_THREADS, GEMM_SMEM>>>(out);
}